// round 15
// baseline (speedup 1.0000x reference)
#include <cuda_runtime.h>
#include <cuda_fp16.h>
#include <math.h>
#include <stdint.h>

// ---------------------------------------------------------------------------
// Problem constants
// ---------------------------------------------------------------------------
#define BATCH   1024
#define CIN     384
#define HDIM    14
#define CDIM    768
#define HEADS   24
#define HD      32
#define WIN     7
#define NTOK    49
#define HID     512
#define MLPD    3072
#define TOKS    (BATCH*NTOK)   // 50176
#define KMERGE  (4*CIN)        // 1536
#define NPIX    (HDIM*HDIM)    // 196

// weight fp16 pool offsets (elements)
#define OFF_MERGE 0
#define SZ_MERGE  (CDIM*KMERGE)
#define OFF_QKV   (OFF_MERGE + SZ_MERGE)
#define SZ_QKV    (2*3*CDIM*CDIM)
#define OFF_PROJ  (OFF_QKV + SZ_QKV)
#define SZ_PROJ   (2*CDIM*CDIM)
#define OFF_FC1   (OFF_PROJ + SZ_PROJ)
#define SZ_FC1    (2*MLPD*CDIM)
#define OFF_FC2   (OFF_FC1 + SZ_FC1)
#define SZ_FC2    (2*CDIM*MLPD)
#define SZ_WPOOL  (OFF_FC2 + SZ_FC2)

// ---------------------------------------------------------------------------
// Scratch
// ---------------------------------------------------------------------------
__device__ __half g_xm16   [(size_t)TOKS * KMERGE];
__device__ __half g_w16    [SZ_WPOOL];
__device__ float  g_h      [(size_t)TOKS * CDIM];
__device__ __half g_h16    [(size_t)TOKS * CDIM];
__device__ __half g_qkv16  [(size_t)TOKS * 3*CDIM];
__device__ __half g_attn16 [(size_t)TOKS * CDIM];
__device__ float  g_tmp    [(size_t)TOKS * CDIM];
__device__ __half g_mlp16  [(size_t)TOKS * MLPD];
__device__ float  g_cpbtab [2 * 169 * HEADS];   // holds 16*sigmoid(cpb)
__device__ float  g_qkvbias[3 * CDIM];

// ---------------------------------------------------------------------------
// helpers
// ---------------------------------------------------------------------------
__device__ __forceinline__ uint32_t smem_u32(const void* p) {
    uint32_t a;
    asm("{ .reg .u64 t; cvta.to.shared.u64 t, %1; cvt.u32.u64 %0, t; }" : "=r"(a) : "l"(p));
    return a;
}
#define SWZ128(off) ((off) ^ (((off) >> 3) & 0x70))

#define CP_ASYNC16(dst, src) \
    asm volatile("cp.async.cg.shared.global [%0], [%1], 16;" :: "r"(dst), "l"(src))
#define CP_COMMIT()  asm volatile("cp.async.commit_group;")
#define CP_WAIT1()   asm volatile("cp.async.wait_group 1;")
#define CP_WAIT0()   asm volatile("cp.async.wait_group 0;")

#define LDSM_X4(r0,r1,r2,r3,addr) \
    asm volatile("ldmatrix.sync.aligned.m8n8.x4.shared.b16 {%0,%1,%2,%3}, [%4];" \
        : "=r"(r0),"=r"(r1),"=r"(r2),"=r"(r3) : "r"(addr))

#define MMA16816(c0,c1,c2,c3,a0,a1,a2,a3,b0,b1) \
    asm volatile("mma.sync.aligned.m16n8k16.row.col.f32.f16.f16.f32 " \
        "{%0,%1,%2,%3},{%4,%5,%6,%7},{%8,%9},{%0,%1,%2,%3};" \
        : "+f"(c0),"+f"(c1),"+f"(c2),"+f"(c3) \
        : "r"(a0),"r"(a1),"r"(a2),"r"(a3),"r"(b0),"r"(b1))

// ---------------------------------------------------------------------------
// HMMA fp16 GEMM:  C[M,N] = A[M,K] @ W[N,K]^T (+bias)(+exact GELU)
// BM=128, BN=256, BK=64; 8 warps (2x4), warp tile 64x64.
// 3-stage cp.async pipeline, one __syncthreads per K-tile.
// Per k16 step: 8 LDSM.x4 feed 32 MMAs (ratio 4.0 vs 2.67 before).
// ---------------------------------------------------------------------------
#define STAGE_BYTES 49152               // A 16KB + B 32KB
#define GSMEM_BYTES (3*STAGE_BYTES)     // 144 KB -> 1 CTA/SM

__global__ __launch_bounds__(256, 1) void gemm16(
    const __half* __restrict__ A, const __half* __restrict__ W,
    const float* __restrict__ bias, float* __restrict__ Cf,
    __half* __restrict__ Ch, int M, int N, int K, int gelu)
{
    extern __shared__ char smem[];
    const uint32_t sb = smem_u32(smem);
    const int tid  = threadIdx.x;
    const int lane = tid & 31;
    const int wid  = tid >> 5;
    const int wm   = wid & 1;          // 0..1 -> 64-row slab
    const int wn   = wid >> 1;         // 0..3 -> 64-col slab
    const int m0   = blockIdx.y * 128;
    const int n0   = blockIdx.x * 256;
    const int KS   = K >> 6;

    const __half* Abase = A + (size_t)m0 * K;
    const __half* Wbase = W + (size_t)n0 * K;

    float acc[4][8][4];
    #pragma unroll
    for (int i = 0; i < 4; i++)
        #pragma unroll
        for (int j = 0; j < 8; j++)
            #pragma unroll
            for (int q = 0; q < 4; q++) acc[i][j][q] = 0.f;

    // chunk c = tid + q*256 -> row = lrow0 + q*32, col = lch*16
    const int lrow0 = tid >> 3;
    const int lch   = tid & 7;
    uint32_t lswz[8];
    #pragma unroll
    for (int q = 0; q < 8; q++)
        lswz[q] = (uint32_t)SWZ128((lrow0 + q * 32) * 128 + lch * 16);

    // A: 4 chunks (128 rows), B: 8 chunks (256 rows)
    #define ISSUE_TILE(it, st) do {                                           \
        const __half* Ag = Abase + (size_t)(it) * 64;                          \
        const __half* Bg = Wbase + (size_t)(it) * 64;                          \
        uint32_t as_ = sb + (st) * STAGE_BYTES;                                \
        uint32_t bs_ = as_ + 16384;                                            \
        _Pragma("unroll")                                                      \
        for (int q = 0; q < 4; q++) {                                          \
            int row = lrow0 + q * 32;                                          \
            const char* ga = (const char*)(Ag + (size_t)row * K) + lch * 16;   \
            CP_ASYNC16(as_ + lswz[q], ga);                                     \
        }                                                                      \
        _Pragma("unroll")                                                      \
        for (int q = 0; q < 8; q++) {                                          \
            int row = lrow0 + q * 32;                                          \
            const char* gb = (const char*)(Bg + (size_t)row * K) + lch * 16;   \
            CP_ASYNC16(bs_ + lswz[q], gb);                                     \
        }                                                                      \
        CP_COMMIT();                                                           \
    } while (0)

    ISSUE_TILE(0, 0);
    ISSUE_TILE(1, 1);

    const int mat = lane >> 3;
    const int l7  = lane & 7;
    int stage = 0;

    for (int it = 0; it < KS; ++it) {
        if (it + 1 < KS) { CP_WAIT1(); } else { CP_WAIT0(); }
        __syncthreads();
        if (it + 2 < KS) {
            int st2 = stage + 2; if (st2 >= 3) st2 -= 3;
            ISSUE_TILE(it + 2, st2);
        }

        const uint32_t as_ = sb + stage * STAGE_BYTES;
        const uint32_t bs_ = as_ + 16384;

        #pragma unroll
        for (int ks = 0; ks < 4; ks++) {
            uint32_t a[4][4];
            #pragma unroll
            for (int mt = 0; mt < 4; mt++) {
                int row = wm * 64 + mt * 16 + (mat & 1) * 8 + l7;
                int kb  = ks * 32 + (mat >> 1) * 16;
                uint32_t ad = as_ + SWZ128(row * 128 + kb);
                LDSM_X4(a[mt][0], a[mt][1], a[mt][2], a[mt][3], ad);
            }
            uint32_t b[8][2];
            #pragma unroll
            for (int ng = 0; ng < 4; ng++) {
                int row = wn * 64 + ng * 16 + (mat >> 1) * 8 + l7;
                int kb  = ks * 32 + (mat & 1) * 16;
                uint32_t bd = bs_ + SWZ128(row * 128 + kb);
                uint32_t r0, r1, r2, r3;
                LDSM_X4(r0, r1, r2, r3, bd);
                b[ng*2  ][0] = r0; b[ng*2  ][1] = r1;
                b[ng*2+1][0] = r2; b[ng*2+1][1] = r3;
            }
            #pragma unroll
            for (int mt = 0; mt < 4; mt++)
                #pragma unroll
                for (int nt = 0; nt < 8; nt++)
                    MMA16816(acc[mt][nt][0], acc[mt][nt][1],
                             acc[mt][nt][2], acc[mt][nt][3],
                             a[mt][0], a[mt][1], a[mt][2], a[mt][3],
                             b[nt][0], b[nt][1]);
        }
        stage++; if (stage >= 3) stage -= 3;
    }

    const int gr = lane >> 2, qp = lane & 3;
    #pragma unroll
    for (int mt = 0; mt < 4; mt++) {
        #pragma unroll
        for (int nt = 0; nt < 8; nt++) {
            const int row0 = m0 + wm * 64 + mt * 16 + gr;
            const int col  = n0 + wn * 64 + nt * 8 + qp * 2;
            float b0 = bias ? bias[col]     : 0.f;
            float b1 = bias ? bias[col + 1] : 0.f;
            float v[4] = { acc[mt][nt][0] + b0, acc[mt][nt][1] + b1,
                           acc[mt][nt][2] + b0, acc[mt][nt][3] + b1 };
            if (gelu) {
                #pragma unroll
                for (int q = 0; q < 4; q++)
                    v[q] = 0.5f * v[q] * (1.0f + erff(v[q] * 0.70710678118654752f));
            }
            const size_t o0 = (size_t)row0 * N + col;
            const size_t o1 = (size_t)(row0 + 8) * N + col;
            if (Cf) { Cf[o0] = v[0]; Cf[o0+1] = v[1]; Cf[o1] = v[2]; Cf[o1+1] = v[3]; }
            if (Ch) {
                Ch[o0]   = __float2half(v[0]); Ch[o0+1] = __float2half(v[1]);
                Ch[o1]   = __float2half(v[2]); Ch[o1+1] = __float2half(v[3]);
            }
        }
    }
}

// ---------------------------------------------------------------------------
// fp32 -> fp16 conversion
// ---------------------------------------------------------------------------
__global__ void to_half(const float* __restrict__ src, __half* __restrict__ dst, size_t n) {
    size_t i = (size_t)blockIdx.x * blockDim.x + threadIdx.x;
    if (i < n) dst[i] = __float2half(src[i]);
}

// ---------------------------------------------------------------------------
// NCHW -> merged-patch rows (fp16), smem-tiled.
// ---------------------------------------------------------------------------
__global__ __launch_bounds__(256) void gather_merge(const float* __restrict__ x) {
    __shared__ float tile[32][NPIX + 1];
    const int b  = blockIdx.y;
    const int c0 = blockIdx.x * 32;
    const int tid = threadIdx.x;

    const float* src = x + ((size_t)b * CIN + c0) * NPIX;
    for (int i = tid; i < 32 * NPIX; i += 256) {
        int c = i / NPIX, p = i - c * NPIX;
        tile[c][p] = src[(size_t)c * NPIX + p];
    }
    __syncthreads();

    for (int i = tid; i < 32 * NPIX; i += 256) {
        int cin  = i & 31;
        int rest = i >> 5;
        int quad = rest & 3;
        int tok  = rest >> 2;
        int ws = quad >> 1, hs = quad & 1;
        int row = (tok / WIN) * 2 + hs;
        int col = (tok % WIN) * 2 + ws;
        g_xm16[((size_t)b * NTOK + tok) * KMERGE + ws * 768 + hs * 384 + c0 + cin]
            = __float2half(tile[cin][row * HDIM + col]);
    }
}

// ---------------------------------------------------------------------------
// LayerNorm over C=768 (R8 measured-good block version).
// ---------------------------------------------------------------------------
template<bool RESIDUAL>
__global__ __launch_bounds__(256) void ln_kernel(
    const float* __restrict__ src, float* __restrict__ dst, __half* __restrict__ dst16,
    const float* __restrict__ g, const float* __restrict__ b)
{
    const int row = blockIdx.x;
    const int tid = threadIdx.x;
    const float* s = src + (size_t)row * CDIM;
    __shared__ float red[32];

    float v[3]; float sum = 0.f;
    #pragma unroll
    for (int i = 0; i < 3; i++) { v[i] = s[tid + i*256]; sum += v[i]; }
    #pragma unroll
    for (int o = 16; o > 0; o >>= 1) sum += __shfl_xor_sync(0xffffffffu, sum, o);
    if ((tid & 31) == 0) red[tid >> 5] = sum;
    __syncthreads();
    if (tid < 32) {
        float t = (tid < 8) ? red[tid] : 0.f;
        #pragma unroll
        for (int o = 4; o > 0; o >>= 1) t += __shfl_xor_sync(0xffffffffu, t, o);
        if (tid == 0) red[0] = t;
    }
    __syncthreads();
    const float mean = red[0] * (1.0f / CDIM);
    __syncthreads();

    float var = 0.f;
    #pragma unroll
    for (int i = 0; i < 3; i++) { float d = v[i] - mean; var += d * d; }
    #pragma unroll
    for (int o = 16; o > 0; o >>= 1) var += __shfl_xor_sync(0xffffffffu, var, o);
    if ((tid & 31) == 0) red[tid >> 5] = var;
    __syncthreads();
    if (tid < 32) {
        float t = (tid < 8) ? red[tid] : 0.f;
        #pragma unroll
        for (int o = 4; o > 0; o >>= 1) t += __shfl_xor_sync(0xffffffffu, t, o);
        if (tid == 0) red[0] = t;
    }
    __syncthreads();
    const float rstd = rsqrtf(red[0] * (1.0f / CDIM) + 1e-5f);

    float* d = dst + (size_t)row * CDIM;
    __half* d16 = dst16 + (size_t)row * CDIM;
    #pragma unroll
    for (int i = 0; i < 3; i++) {
        int c = tid + i * 256;
        float o = (v[i] - mean) * rstd * g[c] + b[c];
        float nv = RESIDUAL ? (d[c] + o) : o;
        d[c] = nv;
        d16[c] = __float2half(nv);
    }
}

// ---------------------------------------------------------------------------
// CPB table; stores 16*sigmoid(rpb).
// ---------------------------------------------------------------------------
__device__ __forceinline__ float cpb_coord(int u) {
    float a = (float)(u - (WIN - 1)) * (8.0f / (float)(WIN - 1));
    float s = (a > 0.f) ? 1.f : ((a < 0.f) ? -1.f : 0.f);
    return s * log2f(fabsf(a) + 1.0f) * (1.0f / 3.0f);
}
__global__ void cpb_kernel(const float* __restrict__ w1, const float* __restrict__ b1,
                           const float* __restrict__ w2)
{
    const int t = blockIdx.x, i = blockIdx.y, j = threadIdx.x;
    __shared__ float hid[HID];
    const float t0 = cpb_coord(t / (2*WIN - 1));
    const float t1 = cpb_coord(t % (2*WIN - 1));
    const float* w1i = w1 + (size_t)i * HID * 2;
    hid[j] = fmaxf(w1i[j*2] * t0 + w1i[j*2 + 1] * t1 + b1[i*HID + j], 0.f);
    __syncthreads();
    if (j < HEADS) {
        const float* w2r = w2 + ((size_t)i * HEADS + j) * HID;
        float s = 0.f;
        for (int q = 0; q < HID; q++) s += w2r[q] * hid[q];
        g_cpbtab[(i * 169 + t) * HEADS + j] = 16.f / (1.f + expf(-s));
    }
}

__global__ void qkvbias_kernel(const float* __restrict__ qb,
                               const float* __restrict__ vb, int i) {
    int c = blockIdx.x * blockDim.x + threadIdx.x;
    if (c >= 3*CDIM) return;
    float v;
    if (c < CDIM)        v = qb[i*CDIM + c];
    else if (c < 2*CDIM) v = 0.f;
    else                 v = vb[i*CDIM + c - 2*CDIM];
    g_qkvbias[c] = v;
}

// ---------------------------------------------------------------------------
// Windowed cosine attention (R8 measured-good version: padded smem + table).
// ---------------------------------------------------------------------------
#define QP 33
__global__ __launch_bounds__(256) void attn_kernel(const float* __restrict__ logit_scale,
                                                   int blk)
{
    const int b = blockIdx.x, head = blockIdx.y, tid = threadIdx.x;
    __shared__ float q[NTOK*QP], k[NTOK*QP], v[NTOK*QP];
    __shared__ float att[NTOK*NTOK];

    const __half* base = g_qkv16 + (size_t)b * NTOK * 3 * CDIM;
    for (int idx = tid; idx < NTOK*HD; idx += 256) {
        int n = idx / HD, d = idx % HD;
        const __half* r = base + (size_t)n * 3 * CDIM + head * HD + d;
        q[n*QP + d] = __half2float(r[0]);
        k[n*QP + d] = __half2float(r[CDIM]);
        v[n*QP + d] = __half2float(r[2*CDIM]);
    }
    __syncthreads();

    const float scale = expf(fminf(logit_scale[blk * HEADS + head], 4.6051702f));
    if (tid < NTOK) {
        float s = 0.f;
        #pragma unroll
        for (int d = 0; d < HD; d++) { float t = q[tid*QP + d]; s += t * t; }
        float r = scale / fmaxf(sqrtf(s), 1e-12f);
        #pragma unroll
        for (int d = 0; d < HD; d++) q[tid*QP + d] *= r;
    } else if (tid >= 64 && tid < 64 + NTOK) {
        int n = tid - 64;
        float s = 0.f;
        #pragma unroll
        for (int d = 0; d < HD; d++) { float t = k[n*QP + d]; s += t * t; }
        float r = 1.f / fmaxf(sqrtf(s), 1e-12f);
        #pragma unroll
        for (int d = 0; d < HD; d++) k[n*QP + d] *= r;
    }
    __syncthreads();

    const float* tab = g_cpbtab + (size_t)blk * 169 * HEADS + head;
    for (int e = tid; e < NTOK*NTOK; e += 256) {
        int n = e / NTOK, m = e - n * NTOK;
        float s = 0.f;
        #pragma unroll
        for (int d = 0; d < HD; d++) s += q[n*QP + d] * k[m*QP + d];
        int yi = n / WIN, xi = n % WIN, yj = m / WIN, xj = m % WIN;
        int r = (yi - yj + WIN - 1) * (2*WIN - 1) + (xi - xj + WIN - 1);
        att[e] = s + tab[(size_t)r * HEADS];
    }
    __syncthreads();

    if (tid < NTOK) {
        float* rw = att + tid * NTOK;
        float mx = -1e30f;
        for (int m = 0; m < NTOK; m++) mx = fmaxf(mx, rw[m]);
        float sum = 0.f;
        for (int m = 0; m < NTOK; m++) { float e = expf(rw[m] - mx); rw[m] = e; sum += e; }
        float inv = 1.f / sum;
        for (int m = 0; m < NTOK; m++) rw[m] *= inv;
    }
    __syncthreads();

    for (int idx = tid; idx < NTOK*HD; idx += 256) {
        int n = idx / HD, d = idx % HD;
        float s = 0.f;
        #pragma unroll
        for (int m = 0; m < NTOK; m++) s += att[n*NTOK + m] * v[m*QP + d];
        g_attn16[((size_t)b * NTOK + n) * CDIM + head * HD + d] = __float2half(s);
    }
}

// ---------------------------------------------------------------------------
// tokens [B,49,768] fp32 -> output NCHW [B,768,7,7], smem-tiled transpose.
// ---------------------------------------------------------------------------
__global__ __launch_bounds__(256) void out_transpose(float* __restrict__ out) {
    __shared__ float tile[NTOK][65];
    const int b  = blockIdx.y;
    const int c0 = blockIdx.x * 64;
    const int tid = threadIdx.x;

    const float* src = g_h + (size_t)b * NTOK * CDIM + c0;
    for (int i = tid; i < NTOK * 64; i += 256) {
        int n = i >> 6, c = i & 63;
        tile[n][c] = src[(size_t)n * CDIM + c];
    }
    __syncthreads();

    float* dst = out + ((size_t)b * CDIM + c0) * NTOK;
    for (int i = tid; i < 64 * NTOK; i += 256) {
        int c = i / NTOK, n = i - c * NTOK;
        dst[(size_t)c * NTOK + n] = tile[n][c];
    }
}

// ---------------------------------------------------------------------------
// Launch
// ---------------------------------------------------------------------------
static inline void conv(const float* s, __half* d, size_t n) {
    to_half<<<(unsigned)((n + 255) / 256), 256>>>(s, d, n);
}

extern "C" void kernel_launch(void* const* d_in, const int* in_sizes, int n_in,
                              void* d_out, int out_size)
{
    const float* x           = (const float*)d_in[0];
    const float* merge_w     = (const float*)d_in[1];
    const float* merge_g     = (const float*)d_in[2];
    const float* merge_b     = (const float*)d_in[3];
    const float* qkv_w       = (const float*)d_in[4];
    const float* q_bias      = (const float*)d_in[5];
    const float* v_bias      = (const float*)d_in[6];
    const float* logit_scale = (const float*)d_in[7];
    const float* cpb_w1      = (const float*)d_in[8];
    const float* cpb_b1      = (const float*)d_in[9];
    const float* cpb_w2      = (const float*)d_in[10];
    const float* proj_w      = (const float*)d_in[11];
    const float* proj_b      = (const float*)d_in[12];
    const float* n1_g        = (const float*)d_in[13];
    const float* n1_b        = (const float*)d_in[14];
    const float* fc1_w       = (const float*)d_in[15];
    const float* fc1_b       = (const float*)d_in[16];
    const float* fc2_w       = (const float*)d_in[17];
    const float* fc2_b       = (const float*)d_in[18];
    const float* n2_g        = (const float*)d_in[19];
    const float* n2_b        = (const float*)d_in[20];
    float* out = (float*)d_out;

    cudaFuncSetAttribute(gemm16, cudaFuncAttributeMaxDynamicSharedMemorySize, GSMEM_BYTES);

    __half *p_xm, *p_w, *p_h16, *p_qkv, *p_attn, *p_mlp;
    float *p_h, *p_tmp, *p_qb;
    cudaGetSymbolAddress((void**)&p_xm,   g_xm16);
    cudaGetSymbolAddress((void**)&p_w,    g_w16);
    cudaGetSymbolAddress((void**)&p_h,    g_h);
    cudaGetSymbolAddress((void**)&p_h16,  g_h16);
    cudaGetSymbolAddress((void**)&p_qkv,  g_qkv16);
    cudaGetSymbolAddress((void**)&p_attn, g_attn16);
    cudaGetSymbolAddress((void**)&p_tmp,  g_tmp);
    cudaGetSymbolAddress((void**)&p_mlp,  g_mlp16);
    cudaGetSymbolAddress((void**)&p_qb,   g_qkvbias);

    conv(merge_w, p_w + OFF_MERGE, SZ_MERGE);                       // 0
    gather_merge<<<dim3(CIN/32, BATCH), 256>>>(x);                  // 1
    conv(qkv_w,   p_w + OFF_QKV,   SZ_QKV);                         // 2
    gemm16<<<dim3(CDIM/256, TOKS/128), 256, GSMEM_BYTES>>>(         // 3
        p_xm, p_w + OFF_MERGE, nullptr, p_tmp, nullptr, TOKS, CDIM, KMERGE, 0);
    conv(proj_w,  p_w + OFF_PROJ,  SZ_PROJ);                        // 4
    conv(fc1_w,   p_w + OFF_FC1,   SZ_FC1);                         // 5
    conv(fc2_w,   p_w + OFF_FC2,   SZ_FC2);                         // 6

    ln_kernel<false><<<TOKS, 256>>>(p_tmp, p_h, p_h16, merge_g, merge_b);
    cpb_kernel<<<dim3(169, 2), HID>>>(cpb_w1, cpb_b1, cpb_w2);

    for (int i = 0; i < 2; i++) {
        qkvbias_kernel<<<(3*CDIM + 255) / 256, 256>>>(q_bias, v_bias, i);
        gemm16<<<dim3(3*CDIM/256, TOKS/128), 256, GSMEM_BYTES>>>(
            p_h16, p_w + OFF_QKV + (size_t)i * 3*CDIM*CDIM, p_qb,
            nullptr, p_qkv, TOKS, 3*CDIM, CDIM, 0);
        attn_kernel<<<dim3(BATCH, HEADS), 256>>>(logit_scale, i);
        gemm16<<<dim3(CDIM/256, TOKS/128), 256, GSMEM_BYTES>>>(
            p_attn, p_w + OFF_PROJ + (size_t)i * CDIM*CDIM, proj_b + i*CDIM,
            p_tmp, nullptr, TOKS, CDIM, CDIM, 0);
        ln_kernel<true><<<TOKS, 256>>>(p_tmp, p_h, p_h16, n1_g + i*CDIM, n1_b + i*CDIM);

        gemm16<<<dim3(MLPD/256, TOKS/128), 256, GSMEM_BYTES>>>(
            p_h16, p_w + OFF_FC1 + (size_t)i * MLPD*CDIM, fc1_b + i*MLPD,
            nullptr, p_mlp, TOKS, MLPD, CDIM, 1);
        gemm16<<<dim3(CDIM/256, TOKS/128), 256, GSMEM_BYTES>>>(
            p_mlp, p_w + OFF_FC2 + (size_t)i * CDIM*MLPD, fc2_b + i*CDIM,
            p_tmp, nullptr, TOKS, CDIM, MLPD, 0);
        ln_kernel<true><<<TOKS, 256>>>(p_tmp, p_h, p_h16, n2_g + i*CDIM, n2_b + i*CDIM);
    }

    out_transpose<<<dim3(CDIM/64, BATCH), 256>>>(out);
}

// round 17
// speedup vs baseline: 1.0757x; 1.0757x over previous
#include <cuda_runtime.h>
#include <cuda_fp16.h>
#include <math.h>
#include <stdint.h>

// ---------------------------------------------------------------------------
// Problem constants
// ---------------------------------------------------------------------------
#define BATCH   1024
#define CIN     384
#define HDIM    14
#define CDIM    768
#define HEADS   24
#define HD      32
#define WIN     7
#define NTOK    49
#define HID     512
#define MLPD    3072
#define TOKS    (BATCH*NTOK)   // 50176
#define KMERGE  (4*CIN)        // 1536
#define NPIX    (HDIM*HDIM)    // 196

// weight fp16 pool offsets (elements)
#define OFF_MERGE 0
#define SZ_MERGE  (CDIM*KMERGE)
#define OFF_QKV   (OFF_MERGE + SZ_MERGE)
#define SZ_QKV    (2*3*CDIM*CDIM)
#define OFF_PROJ  (OFF_QKV + SZ_QKV)
#define SZ_PROJ   (2*CDIM*CDIM)
#define OFF_FC1   (OFF_PROJ + SZ_PROJ)
#define SZ_FC1    (2*MLPD*CDIM)
#define OFF_FC2   (OFF_FC1 + SZ_FC1)
#define SZ_FC2    (2*CDIM*MLPD)
#define SZ_WPOOL  (OFF_FC2 + SZ_FC2)

// ---------------------------------------------------------------------------
// Scratch
// ---------------------------------------------------------------------------
__device__ __half g_xm16   [(size_t)TOKS * KMERGE];
__device__ __half g_w16    [SZ_WPOOL];
__device__ float  g_h      [(size_t)TOKS * CDIM];
__device__ __half g_h16    [(size_t)TOKS * CDIM];
__device__ __half g_qkv16  [(size_t)TOKS * 3*CDIM];
__device__ __half g_attn16 [(size_t)TOKS * CDIM];
__device__ float  g_tmp    [(size_t)TOKS * CDIM];
__device__ __half g_mlp16  [(size_t)TOKS * MLPD];
__device__ float  g_cpbtab [2 * 169 * HEADS];   // holds 16*sigmoid(cpb)
__device__ float  g_qkvbias[3 * CDIM];

// ---------------------------------------------------------------------------
// helpers
// ---------------------------------------------------------------------------
__device__ __forceinline__ uint32_t smem_u32(const void* p) {
    uint32_t a;
    asm("{ .reg .u64 t; cvta.to.shared.u64 t, %1; cvt.u32.u64 %0, t; }" : "=r"(a) : "l"(p));
    return a;
}
#define SWZ128(off) ((off) ^ (((off) >> 3) & 0x70))

#define CP_ASYNC16(dst, src) \
    asm volatile("cp.async.cg.shared.global [%0], [%1], 16;" :: "r"(dst), "l"(src))
#define CP_COMMIT()  asm volatile("cp.async.commit_group;")
#define CP_WAIT1()   asm volatile("cp.async.wait_group 1;")
#define CP_WAIT0()   asm volatile("cp.async.wait_group 0;")

#define LDSM_X4(r0,r1,r2,r3,addr) \
    asm volatile("ldmatrix.sync.aligned.m8n8.x4.shared.b16 {%0,%1,%2,%3}, [%4];" \
        : "=r"(r0),"=r"(r1),"=r"(r2),"=r"(r3) : "r"(addr))

#define MMA16816(c0,c1,c2,c3,a0,a1,a2,a3,b0,b1) \
    asm volatile("mma.sync.aligned.m16n8k16.row.col.f32.f16.f16.f32 " \
        "{%0,%1,%2,%3},{%4,%5,%6,%7},{%8,%9},{%0,%1,%2,%3};" \
        : "+f"(c0),"+f"(c1),"+f"(c2),"+f"(c3) \
        : "r"(a0),"r"(a1),"r"(a2),"r"(a3),"r"(b0),"r"(b1))

__device__ __forceinline__ float warp_sum(float v) {
    #pragma unroll
    for (int o = 16; o > 0; o >>= 1) v += __shfl_xor_sync(0xffffffffu, v, o);
    return v;
}
__device__ __forceinline__ float warp_max(float v) {
    #pragma unroll
    for (int o = 16; o > 0; o >>= 1) v = fmaxf(v, __shfl_xor_sync(0xffffffffu, v, o));
    return v;
}

// ---------------------------------------------------------------------------
// HMMA fp16 GEMM — EXACT R8 config (measured 400 TF/s, 66.6% tensor).
// BM=BN=128, BK=64, 256 threads (2x4 warps, 64x32 tiles), 3-stage cp.async.
// ---------------------------------------------------------------------------
#define STAGE_BYTES 32768
#define GSMEM_BYTES (3*STAGE_BYTES)

__global__ __launch_bounds__(256, 2) void gemm16(
    const __half* __restrict__ A, const __half* __restrict__ W,
    const float* __restrict__ bias, float* __restrict__ Cf,
    __half* __restrict__ Ch, int M, int N, int K, int gelu)
{
    extern __shared__ char smem[];
    const uint32_t sb = smem_u32(smem);
    const int tid  = threadIdx.x;
    const int lane = tid & 31;
    const int wid  = tid >> 5;
    const int wm   = wid & 1;
    const int wn   = wid >> 1;
    const int m0   = blockIdx.y * 128;
    const int n0   = blockIdx.x * 128;
    const int KS   = K >> 6;

    const __half* Abase = A + (size_t)m0 * K;
    const __half* Wbase = W + (size_t)n0 * K;

    float acc[4][4][4];
    #pragma unroll
    for (int i = 0; i < 4; i++)
        #pragma unroll
        for (int j = 0; j < 4; j++)
            #pragma unroll
            for (int q = 0; q < 4; q++) acc[i][j][q] = 0.f;

    const int lrow0 = tid >> 3;
    const int lch   = tid & 7;
    const uint32_t lswz[4] = {
        (uint32_t)SWZ128((lrow0 +  0) * 128 + lch * 16),
        (uint32_t)SWZ128((lrow0 + 32) * 128 + lch * 16),
        (uint32_t)SWZ128((lrow0 + 64) * 128 + lch * 16),
        (uint32_t)SWZ128((lrow0 + 96) * 128 + lch * 16)
    };

    #define ISSUE_TILE(it, st) do {                                           \
        const __half* Ag = Abase + (size_t)(it) * 64;                          \
        const __half* Bg = Wbase + (size_t)(it) * 64;                          \
        uint32_t as_ = sb + (st) * STAGE_BYTES;                                \
        uint32_t bs_ = as_ + 16384;                                            \
        _Pragma("unroll")                                                      \
        for (int q = 0; q < 4; q++) {                                          \
            int row = lrow0 + q * 32;                                          \
            const char* ga = (const char*)(Ag + (size_t)row * K) + lch * 16;   \
            const char* gb = (const char*)(Bg + (size_t)row * K) + lch * 16;   \
            CP_ASYNC16(as_ + lswz[q], ga);                                     \
            CP_ASYNC16(bs_ + lswz[q], gb);                                     \
        }                                                                      \
        CP_COMMIT();                                                           \
    } while (0)

    ISSUE_TILE(0, 0);
    ISSUE_TILE(1, 1);

    const int mat = lane >> 3;
    const int l7  = lane & 7;
    int stage = 0;

    for (int it = 0; it < KS; ++it) {
        if (it + 1 < KS) { CP_WAIT1(); } else { CP_WAIT0(); }
        __syncthreads();
        if (it + 2 < KS) {
            int st2 = stage + 2; if (st2 >= 3) st2 -= 3;
            ISSUE_TILE(it + 2, st2);
        }

        const uint32_t as_ = sb + stage * STAGE_BYTES;
        const uint32_t bs_ = as_ + 16384;

        #pragma unroll
        for (int ks = 0; ks < 4; ks++) {
            uint32_t a[4][4];
            #pragma unroll
            for (int mt = 0; mt < 4; mt++) {
                int row = wm * 64 + mt * 16 + (mat & 1) * 8 + l7;
                int kb  = ks * 32 + (mat >> 1) * 16;
                uint32_t ad = as_ + SWZ128(row * 128 + kb);
                LDSM_X4(a[mt][0], a[mt][1], a[mt][2], a[mt][3], ad);
            }
            uint32_t b[4][2];
            #pragma unroll
            for (int ng = 0; ng < 2; ng++) {
                int row = wn * 32 + ng * 16 + (mat >> 1) * 8 + l7;
                int kb  = ks * 32 + (mat & 1) * 16;
                uint32_t bd = bs_ + SWZ128(row * 128 + kb);
                uint32_t r0, r1, r2, r3;
                LDSM_X4(r0, r1, r2, r3, bd);
                b[ng*2  ][0] = r0; b[ng*2  ][1] = r1;
                b[ng*2+1][0] = r2; b[ng*2+1][1] = r3;
            }
            #pragma unroll
            for (int mt = 0; mt < 4; mt++)
                #pragma unroll
                for (int nt = 0; nt < 4; nt++)
                    MMA16816(acc[mt][nt][0], acc[mt][nt][1],
                             acc[mt][nt][2], acc[mt][nt][3],
                             a[mt][0], a[mt][1], a[mt][2], a[mt][3],
                             b[nt][0], b[nt][1]);
        }
        stage++; if (stage >= 3) stage -= 3;
    }

    const int gr = lane >> 2, qp = lane & 3;
    #pragma unroll
    for (int mt = 0; mt < 4; mt++) {
        #pragma unroll
        for (int nt = 0; nt < 4; nt++) {
            const int row0 = m0 + wm * 64 + mt * 16 + gr;
            const int col  = n0 + wn * 32 + nt * 8 + qp * 2;
            float b0 = bias ? bias[col]     : 0.f;
            float b1 = bias ? bias[col + 1] : 0.f;
            float v[4] = { acc[mt][nt][0] + b0, acc[mt][nt][1] + b1,
                           acc[mt][nt][2] + b0, acc[mt][nt][3] + b1 };
            if (gelu) {
                #pragma unroll
                for (int q = 0; q < 4; q++)
                    v[q] = 0.5f * v[q] * (1.0f + erff(v[q] * 0.70710678118654752f));
            }
            const size_t o0 = (size_t)row0 * N + col;
            const size_t o1 = (size_t)(row0 + 8) * N + col;
            if (Cf) { Cf[o0] = v[0]; Cf[o0+1] = v[1]; Cf[o1] = v[2]; Cf[o1+1] = v[3]; }
            if (Ch) {
                Ch[o0]   = __float2half(v[0]); Ch[o0+1] = __float2half(v[1]);
                Ch[o1]   = __float2half(v[2]); Ch[o1+1] = __float2half(v[3]);
            }
        }
    }
}

// ---------------------------------------------------------------------------
// fp32 -> fp16 conversion
// ---------------------------------------------------------------------------
__global__ void to_half(const float* __restrict__ src, __half* __restrict__ dst, size_t n) {
    size_t i = (size_t)blockIdx.x * blockDim.x + threadIdx.x;
    if (i < n) dst[i] = __float2half(src[i]);
}

// ---------------------------------------------------------------------------
// NCHW -> merged-patch rows (fp16), smem-tiled.
// ---------------------------------------------------------------------------
__global__ __launch_bounds__(256) void gather_merge(const float* __restrict__ x) {
    __shared__ float tile[32][NPIX + 1];
    const int b  = blockIdx.y;
    const int c0 = blockIdx.x * 32;
    const int tid = threadIdx.x;

    const float* src = x + ((size_t)b * CIN + c0) * NPIX;
    for (int i = tid; i < 32 * NPIX; i += 256) {
        int c = i / NPIX, p = i - c * NPIX;
        tile[c][p] = src[(size_t)c * NPIX + p];
    }
    __syncthreads();

    for (int i = tid; i < 32 * NPIX; i += 256) {
        int cin  = i & 31;
        int rest = i >> 5;
        int quad = rest & 3;
        int tok  = rest >> 2;
        int ws = quad >> 1, hs = quad & 1;
        int row = (tok / WIN) * 2 + hs;
        int col = (tok % WIN) * 2 + ws;
        g_xm16[((size_t)b * NTOK + tok) * KMERGE + ws * 768 + hs * 384 + c0 + cin]
            = __float2half(tile[cin][row * HDIM + col]);
    }
}

// ---------------------------------------------------------------------------
// LayerNorm over C=768 (R8 measured-good block version).
// ---------------------------------------------------------------------------
template<bool RESIDUAL>
__global__ __launch_bounds__(256) void ln_kernel(
    const float* __restrict__ src, float* __restrict__ dst, __half* __restrict__ dst16,
    const float* __restrict__ g, const float* __restrict__ b)
{
    const int row = blockIdx.x;
    const int tid = threadIdx.x;
    const float* s = src + (size_t)row * CDIM;
    __shared__ float red[32];

    float v[3]; float sum = 0.f;
    #pragma unroll
    for (int i = 0; i < 3; i++) { v[i] = s[tid + i*256]; sum += v[i]; }
    #pragma unroll
    for (int o = 16; o > 0; o >>= 1) sum += __shfl_xor_sync(0xffffffffu, sum, o);
    if ((tid & 31) == 0) red[tid >> 5] = sum;
    __syncthreads();
    if (tid < 32) {
        float t = (tid < 8) ? red[tid] : 0.f;
        #pragma unroll
        for (int o = 4; o > 0; o >>= 1) t += __shfl_xor_sync(0xffffffffu, t, o);
        if (tid == 0) red[0] = t;
    }
    __syncthreads();
    const float mean = red[0] * (1.0f / CDIM);
    __syncthreads();

    float var = 0.f;
    #pragma unroll
    for (int i = 0; i < 3; i++) { float d = v[i] - mean; var += d * d; }
    #pragma unroll
    for (int o = 16; o > 0; o >>= 1) var += __shfl_xor_sync(0xffffffffu, var, o);
    if ((tid & 31) == 0) red[tid >> 5] = var;
    __syncthreads();
    if (tid < 32) {
        float t = (tid < 8) ? red[tid] : 0.f;
        #pragma unroll
        for (int o = 4; o > 0; o >>= 1) t += __shfl_xor_sync(0xffffffffu, t, o);
        if (tid == 0) red[0] = t;
    }
    __syncthreads();
    const float rstd = rsqrtf(red[0] * (1.0f / CDIM) + 1e-5f);

    float* d = dst + (size_t)row * CDIM;
    __half* d16 = dst16 + (size_t)row * CDIM;
    #pragma unroll
    for (int i = 0; i < 3; i++) {
        int c = tid + i * 256;
        float o = (v[i] - mean) * rstd * g[c] + b[c];
        float nv = RESIDUAL ? (d[c] + o) : o;
        d[c] = nv;
        d16[c] = __float2half(nv);
    }
}

// ---------------------------------------------------------------------------
// CPB table; stores 16*sigmoid(rpb).
// ---------------------------------------------------------------------------
__device__ __forceinline__ float cpb_coord(int u) {
    float a = (float)(u - (WIN - 1)) * (8.0f / (float)(WIN - 1));
    float s = (a > 0.f) ? 1.f : ((a < 0.f) ? -1.f : 0.f);
    return s * log2f(fabsf(a) + 1.0f) * (1.0f / 3.0f);
}
__global__ void cpb_kernel(const float* __restrict__ w1, const float* __restrict__ b1,
                           const float* __restrict__ w2)
{
    const int t = blockIdx.x, i = blockIdx.y, j = threadIdx.x;
    __shared__ float hid[HID];
    const float t0 = cpb_coord(t / (2*WIN - 1));
    const float t1 = cpb_coord(t % (2*WIN - 1));
    const float* w1i = w1 + (size_t)i * HID * 2;
    hid[j] = fmaxf(w1i[j*2] * t0 + w1i[j*2 + 1] * t1 + b1[i*HID + j], 0.f);
    __syncthreads();
    if (j < HEADS) {
        const float* w2r = w2 + ((size_t)i * HEADS + j) * HID;
        float s = 0.f;
        for (int q = 0; q < HID; q++) s += w2r[q] * hid[q];
        g_cpbtab[(i * 169 + t) * HEADS + j] = 16.f / (1.f + expf(-s));
    }
}

__global__ void qkvbias_kernel(const float* __restrict__ qb,
                               const float* __restrict__ vb, int i) {
    int c = blockIdx.x * blockDim.x + threadIdx.x;
    if (c >= 3*CDIM) return;
    float v;
    if (c < CDIM)        v = qb[i*CDIM + c];
    else if (c < 2*CDIM) v = 0.f;
    else                 v = vb[i*CDIM + c - 2*CDIM];
    g_qkvbias[c] = v;
}

// ---------------------------------------------------------------------------
// Windowed cosine attention v2 — register-blocked.
// Each lane holds K rows (lane, lane+32) in registers (normalized locally);
// warp w computes att rows n = w, w+8, ... with q broadcast from smem;
// softmax fused in registers via warp shuffles; AV with V columns in regs.
// ---------------------------------------------------------------------------
#define QP 33
__global__ __launch_bounds__(256) void attn_kernel(const float* __restrict__ logit_scale,
                                                   int blk)
{
    const int b = blockIdx.x, head = blockIdx.y, tid = threadIdx.x;
    const int lane = tid & 31, w = tid >> 5;
    __shared__ float q[NTOK*QP], k[NTOK*QP], v[NTOK*QP];
    __shared__ float att[NTOK*NTOK];

    // stage qkv (coalesced: lane = d)
    const __half* base = g_qkv16 + (size_t)b * NTOK * 3 * CDIM + head * HD;
    for (int idx = tid; idx < NTOK*HD; idx += 256) {
        int n = idx >> 5, d = idx & 31;
        const __half* r = base + (size_t)n * 3 * CDIM + d;
        q[n*QP + d] = __half2float(r[0]);
        k[n*QP + d] = __half2float(r[CDIM]);
        v[n*QP + d] = __half2float(r[2*CDIM]);
    }
    __syncthreads();

    // q rows: normalize in smem, scale folded (conflict-free, measured-good)
    const float scale = __expf(fminf(logit_scale[blk * HEADS + head], 4.6051702f));
    if (tid < NTOK) {
        float s = 0.f;
        #pragma unroll
        for (int d = 0; d < HD; d++) { float t = q[tid*QP + d]; s += t * t; }
        float r = scale / fmaxf(sqrtf(s), 1e-12f);
        #pragma unroll
        for (int d = 0; d < HD; d++) q[tid*QP + d] *= r;
    }
    __syncthreads();

    // K rows in registers, normalized locally (no reduction needed)
    const int m1 = lane + 32;
    const bool has1 = (m1 < NTOK);
    float k0[HD], k1[HD];
    {
        float s0 = 0.f, s1 = 0.f;
        #pragma unroll
        for (int d = 0; d < HD; d++) { k0[d] = k[lane*QP + d]; s0 += k0[d]*k0[d]; }
        #pragma unroll
        for (int d = 0; d < HD; d++) { k1[d] = has1 ? k[m1*QP + d] : 0.f; s1 += k1[d]*k1[d]; }
        float r0 = 1.f / fmaxf(sqrtf(s0), 1e-12f);
        float r1 = 1.f / fmaxf(sqrtf(s1), 1e-12f);
        #pragma unroll
        for (int d = 0; d < HD; d++) { k0[d] *= r0; k1[d] *= r1; }
    }

    // QK + fused softmax (per-warp rows)
    const float* tab = g_cpbtab + (size_t)blk * 169 * HEADS + head;
    const int yj0 = lane / WIN, xj0 = lane % WIN;
    const int yj1 = has1 ? m1 / WIN : 0, xj1 = has1 ? m1 % WIN : 0;
    for (int n = w; n < NTOK; n += 8) {
        const int yi = n / WIN, xi = n % WIN;
        float s0 = 0.f, s1 = 0.f;
        #pragma unroll
        for (int d = 0; d < HD; d++) {
            float qd = q[n*QP + d];
            s0 += qd * k0[d];
            s1 += qd * k1[d];
        }
        s0 += tab[(size_t)((yi - yj0 + 6) * 13 + (xi - xj0 + 6)) * HEADS];
        if (has1) s1 += tab[(size_t)((yi - yj1 + 6) * 13 + (xi - xj1 + 6)) * HEADS];
        else      s1 = -1e30f;
        float mx  = warp_max(fmaxf(s0, s1));
        float e0  = __expf(s0 - mx);
        float e1  = has1 ? __expf(s1 - mx) : 0.f;
        float inv = 1.f / warp_sum(e0 + e1);
        att[n*NTOK + lane] = e0 * inv;
        if (has1) att[n*NTOK + m1] = e1 * inv;
    }
    __syncthreads();

    // AV: V column d=lane in registers; att broadcast
    float vc[NTOK];
    #pragma unroll
    for (int m = 0; m < NTOK; m++) vc[m] = v[m*QP + lane];
    for (int n = w; n < NTOK; n += 8) {
        float acc = 0.f;
        #pragma unroll
        for (int m = 0; m < NTOK; m++) acc += att[n*NTOK + m] * vc[m];
        g_attn16[((size_t)b * NTOK + n) * CDIM + head * HD + lane] = __float2half(acc);
    }
}

// ---------------------------------------------------------------------------
// tokens [B,49,768] fp32 -> output NCHW [B,768,7,7], smem-tiled transpose.
// ---------------------------------------------------------------------------
__global__ __launch_bounds__(256) void out_transpose(float* __restrict__ out) {
    __shared__ float tile[NTOK][65];
    const int b  = blockIdx.y;
    const int c0 = blockIdx.x * 64;
    const int tid = threadIdx.x;

    const float* src = g_h + (size_t)b * NTOK * CDIM + c0;
    for (int i = tid; i < NTOK * 64; i += 256) {
        int n = i >> 6, c = i & 63;
        tile[n][c] = src[(size_t)n * CDIM + c];
    }
    __syncthreads();

    float* dst = out + ((size_t)b * CDIM + c0) * NTOK;
    for (int i = tid; i < 64 * NTOK; i += 256) {
        int c = i / NTOK, n = i - c * NTOK;
        dst[(size_t)c * NTOK + n] = tile[n][c];
    }
}

// ---------------------------------------------------------------------------
// Launch
// ---------------------------------------------------------------------------
static inline void conv(const float* s, __half* d, size_t n) {
    to_half<<<(unsigned)((n + 255) / 256), 256>>>(s, d, n);
}

extern "C" void kernel_launch(void* const* d_in, const int* in_sizes, int n_in,
                              void* d_out, int out_size)
{
    const float* x           = (const float*)d_in[0];
    const float* merge_w     = (const float*)d_in[1];
    const float* merge_g     = (const float*)d_in[2];
    const float* merge_b     = (const float*)d_in[3];
    const float* qkv_w       = (const float*)d_in[4];
    const float* q_bias      = (const float*)d_in[5];
    const float* v_bias      = (const float*)d_in[6];
    const float* logit_scale = (const float*)d_in[7];
    const float* cpb_w1      = (const float*)d_in[8];
    const float* cpb_b1      = (const float*)d_in[9];
    const float* cpb_w2      = (const float*)d_in[10];
    const float* proj_w      = (const float*)d_in[11];
    const float* proj_b      = (const float*)d_in[12];
    const float* n1_g        = (const float*)d_in[13];
    const float* n1_b        = (const float*)d_in[14];
    const float* fc1_w       = (const float*)d_in[15];
    const float* fc1_b       = (const float*)d_in[16];
    const float* fc2_w       = (const float*)d_in[17];
    const float* fc2_b       = (const float*)d_in[18];
    const float* n2_g        = (const float*)d_in[19];
    const float* n2_b        = (const float*)d_in[20];
    float* out = (float*)d_out;

    cudaFuncSetAttribute(gemm16, cudaFuncAttributeMaxDynamicSharedMemorySize, GSMEM_BYTES);

    __half *p_xm, *p_w, *p_h16, *p_qkv, *p_attn, *p_mlp;
    float *p_h, *p_tmp, *p_qb;
    cudaGetSymbolAddress((void**)&p_xm,   g_xm16);
    cudaGetSymbolAddress((void**)&p_w,    g_w16);
    cudaGetSymbolAddress((void**)&p_h,    g_h);
    cudaGetSymbolAddress((void**)&p_h16,  g_h16);
    cudaGetSymbolAddress((void**)&p_qkv,  g_qkv16);
    cudaGetSymbolAddress((void**)&p_attn, g_attn16);
    cudaGetSymbolAddress((void**)&p_tmp,  g_tmp);
    cudaGetSymbolAddress((void**)&p_mlp,  g_mlp16);
    cudaGetSymbolAddress((void**)&p_qb,   g_qkvbias);

    conv(merge_w, p_w + OFF_MERGE, SZ_MERGE);                       // 0
    gather_merge<<<dim3(CIN/32, BATCH), 256>>>(x);                  // 1
    conv(qkv_w,   p_w + OFF_QKV,   SZ_QKV);                         // 2
    gemm16<<<dim3(CDIM/128, TOKS/128), 256, GSMEM_BYTES>>>(         // 3
        p_xm, p_w + OFF_MERGE, nullptr, p_tmp, nullptr, TOKS, CDIM, KMERGE, 0);
    conv(proj_w,  p_w + OFF_PROJ,  SZ_PROJ);                        // 4
    conv(fc1_w,   p_w + OFF_FC1,   SZ_FC1);                         // 5
    conv(fc2_w,   p_w + OFF_FC2,   SZ_FC2);                         // 6

    ln_kernel<false><<<TOKS, 256>>>(p_tmp, p_h, p_h16, merge_g, merge_b);
    cpb_kernel<<<dim3(169, 2), HID>>>(cpb_w1, cpb_b1, cpb_w2);

    for (int i = 0; i < 2; i++) {
        qkvbias_kernel<<<(3*CDIM + 255) / 256, 256>>>(q_bias, v_bias, i);
        gemm16<<<dim3(3*CDIM/128, TOKS/128), 256, GSMEM_BYTES>>>(
            p_h16, p_w + OFF_QKV + (size_t)i * 3*CDIM*CDIM, p_qb,
            nullptr, p_qkv, TOKS, 3*CDIM, CDIM, 0);
        attn_kernel<<<dim3(BATCH, HEADS), 256>>>(logit_scale, i);
        gemm16<<<dim3(CDIM/128, TOKS/128), 256, GSMEM_BYTES>>>(
            p_attn, p_w + OFF_PROJ + (size_t)i * CDIM*CDIM, proj_b + i*CDIM,
            p_tmp, nullptr, TOKS, CDIM, CDIM, 0);
        ln_kernel<true><<<TOKS, 256>>>(p_tmp, p_h, p_h16, n1_g + i*CDIM, n1_b + i*CDIM);

        gemm16<<<dim3(MLPD/128, TOKS/128), 256, GSMEM_BYTES>>>(
            p_h16, p_w + OFF_FC1 + (size_t)i * MLPD*CDIM, fc1_b + i*MLPD,
            nullptr, p_mlp, TOKS, MLPD, CDIM, 1);
        gemm16<<<dim3(CDIM/128, TOKS/128), 256, GSMEM_BYTES>>>(
            p_mlp, p_w + OFF_FC2 + (size_t)i * CDIM*MLPD, fc2_b + i*CDIM,
            p_tmp, nullptr, TOKS, CDIM, MLPD, 0);
        ln_kernel<true><<<TOKS, 256>>>(p_tmp, p_h, p_h16, n2_g + i*CDIM, n2_b + i*CDIM);
    }

    out_transpose<<<dim3(CDIM/64, BATCH), 256>>>(out);
}